// round 16
// baseline (speedup 1.0000x reference)
#include <cuda_runtime.h>
#include <cstddef>

// ---------------- problem constants ----------------
#define BB   64
#define TT   1024
#define II   128
#define HH   512
#define KK   640            // I + H

// ---------------- partitioning ----------------
#define GH   32             // hidden groups
#define GB   4              // batch groups
#define NCTA (GH*GB)        // 128 CTAs, one per SM, all resident
#define UH   16             // hidden units per CTA
#define UB   16             // batches per CTA
#define NTHR 512            // 16 warps: warp = (ug 0..7, bg2 0..1); lane = (ks 0..15, e 0..1)

#define WST  642            // weight row stride (floats), even -> ull rows aligned
#define HST  516            // h row stride (floats): even, 16B-aligned rows, %32==4

typedef unsigned long long ull;

// persistent state (no cudaMalloc allowed)
__device__ float    g_Hbuf[2][BB*HH];
__device__ unsigned g_flag[GB][32];   // per-group arrival flags, one 128B line per group

// ---------------- packed fp32x2 + fast helpers ----------------
__device__ __forceinline__ ull ffma2(ull a, ull b, ull c) {
    ull d;
    asm("fma.rn.f32x2 %0, %1, %2, %3;" : "=l"(d) : "l"(a), "l"(b), "l"(c));
    return d;
}
__device__ __forceinline__ ull add2(ull a, ull b) {
    ull d;
    asm("add.rn.f32x2 %0, %1, %2;" : "=l"(d) : "l"(a), "l"(b));
    return d;
}
__device__ __forceinline__ float red2(ull v) {
    return __uint_as_float((unsigned)v) + __uint_as_float((unsigned)(v >> 32));
}
__device__ __forceinline__ ull shflx(ull v, int m) {
    unsigned lo = (unsigned)v, hi = (unsigned)(v >> 32);
    lo = __shfl_xor_sync(0xffffffffu, lo, m);
    hi = __shfl_xor_sync(0xffffffffu, hi, m);
    return ((ull)hi << 32) | (ull)lo;
}
__device__ __forceinline__ float tanha(float x) {
    float y; asm("tanh.approx.f32 %0, %1;" : "=f"(y) : "f"(x)); return y;
}
__device__ __forceinline__ float sigm(float x) {
    return fmaf(tanha(0.5f * x), 0.5f, 0.5f);
}
__device__ __forceinline__ unsigned ld_acq(const unsigned* p) {
    unsigned v;
    asm volatile("ld.acquire.gpu.global.u32 %0, [%1];" : "=r"(v) : "l"(p) : "memory");
    return v;
}

__global__ void slstm_init_kernel() {
    if (threadIdx.x < GB * 32) ((unsigned*)g_flag)[threadIdx.x] = 0u;
}

// ---------------- persistent sLSTM kernel ----------------
extern "C" __global__ void __launch_bounds__(NTHR, 1)
sLSTM_70772471103948_kernel(const float* __restrict__ x,     // [B,T,I]
                            const float* __restrict__ W_ih,  // [4H,I]
                            const float* __restrict__ W_hh,  // [4H,H]
                            const float* __restrict__ b_ih,  // [4H]
                            const float* __restrict__ b_hh,  // [4H]
                            const float* __restrict__ Wf,    // [H,H]
                            const float* __restrict__ bf,    // [H]
                            float* __restrict__ out,         // [B,T,H] | h[B,H] | c[B,H]
                            long long out_elems)
{
    extern __shared__ float smem[];
    float* Wsm = smem;                           // 64 rows x WST (gate weights, [x|h] cols)
    float* hx  = smem + 64 * WST;                // 16 batch rows x HST (h_t only)

    const int tid  = threadIdx.x;
    const int w    = tid >> 5;
    const int lane = tid & 31;
    const int ks   = lane & 15;                  // k-slice
    const int e    = lane >> 4;                  // batch parity
    const int ug   = w & 7;                      // u-pair group (u in {2ug, 2ug+1})
    const int bg2  = w >> 3;                     // batch octet (0/1)
    const int hg   = blockIdx.x & (GH - 1);
    const int bg   = blockIdx.x >> 5;
    const int j0   = hg * UH;
    const int b0   = bg * UB;

    // lane's owned element after shfl reduction
    const int uj = ks >> 3;
    const int ib = (ks >> 1) & 3;
    const int jl = j0 + 2 * ug + uj;             // owned hidden index
    const int bl = b0 + bg2 * 8 + 2 * ib + e;    // owned global batch

    // ---- stage gate weights into SMEM once ----
    for (int idx = tid; idx < 64 * KK; idx += NTHR) {
        int r  = idx / KK;
        int k  = idx - r * KK;
        int gg = r >> 4, uu = r & 15;
        int grow = gg * HH + j0 + uu;            // gate order: i,f,g,o
        float wv = (k < II) ? W_ih[grow * II + k] : W_hh[grow * HH + (k - II)];
        Wsm[r * WST + k] = wv;
    }
    // ---- h_0 = 0 ----
    {
        float4 z = make_float4(0.f, 0.f, 0.f, 0.f);
        #pragma unroll
        for (int it = 0; it < (UB * HH / 4) / NTHR; it++) {
            int idx = tid + it * NTHR;
            int bb = idx >> 7, kk4 = idx & 127;
            *(float4*)(hx + bb * HST + kk4 * 4) = z;
        }
    }
    const float bias0 = b_ih[0 * HH + jl] + b_hh[0 * HH + jl];
    const float bias1 = b_ih[1 * HH + jl] + b_hh[1 * HH + jl];
    const float bias2 = b_ih[2 * HH + jl] + b_hh[2 * HH + jl];
    const float bias3 = b_ih[3 * HH + jl] + b_hh[3 * HH + jl];
    const float bfj   = bf[jl];

    __syncthreads();

    // base pointers (lane-strided coalesced k)
    const ull* pw  = (const ull*)Wsm + (size_t)ug * WST + ks;          // + (g*16+u2)*321 + [64+] m*16
    const ull* pv  = (const ull*)hx + (size_t)(bg2 * 8 + e) * (HST/2) + ks; // + i*HST + m*16
    const ull* pwf = (const ull*)(Wf + (size_t)(j0 + 2 * ug) * HH) + ks;    // + u2*256 + m*16
    const ull* xu  = (const ull*)x;
    const int  bl0 = b0 + bg2 * 8 + e;           // base batch for value rows (rows bl0 + 2i)

    unsigned* myflag  = &g_flag[bg][hg];
    unsigned* flags   = &g_flag[bg][0];

    float cc = 0.f, hv = 0.f;                    // owned (jl, bl) state; cc RAW (fe deferred)

    // ===== prologue: x-part of gates(t=0) =====
    ull acc[32];                                 // idx = (u2*4 + i)*4 + g
    #pragma unroll
    for (int i = 0; i < 32; i++) acc[i] = 0ull;
    #pragma unroll
    for (int m = 0; m < 4; m++) {
        ull wr[8];
        #pragma unroll
        for (int g = 0; g < 4; g++) {
            wr[g * 2 + 0] = pw[(g * 16 + 0) * (WST/2) + m * 16];
            wr[g * 2 + 1] = pw[(g * 16 + 1) * (WST/2) + m * 16];
        }
        #pragma unroll
        for (int i = 0; i < 4; i++) {
            ull v = __ldg(xu + ((size_t)(bl0 + 2 * i) * TT + 0) * (II/2) + ks + m * 16);
            #pragma unroll
            for (int g = 0; g < 4; g++) {
                acc[(0 * 4 + i) * 4 + g] = ffma2(wr[g * 2 + 0], v, acc[(0 * 4 + i) * 4 + g]);
                acc[(1 * 4 + i) * 4 + g] = ffma2(wr[g * 2 + 1], v, acc[(1 * 4 + i) * 4 + g]);
            }
        }
    }

    #pragma unroll 1
    for (int t = 0; t < TT; t++) {
        // ===== h-part of gates(t) + fused fe(h_{t-1}) =====
        ull fac[8];                              // idx = u2*4 + i
        #pragma unroll
        for (int i = 0; i < 8; i++) fac[i] = 0ull;

        #pragma unroll
        for (int m = 0; m < 16; m++) {
            ull wr[8];
            #pragma unroll
            for (int g = 0; g < 4; g++) {
                wr[g * 2 + 0] = pw[(g * 16 + 0) * (WST/2) + 64 + m * 16];
                wr[g * 2 + 1] = pw[(g * 16 + 1) * (WST/2) + 64 + m * 16];
            }
            ull wf0 = __ldg(pwf + m * 16);
            ull wf1 = __ldg(pwf + 256 + m * 16);
            #pragma unroll
            for (int i = 0; i < 4; i++) {
                ull v = pv[i * HST + m * 16];    // h row: batch bl0 + 2i
                #pragma unroll
                for (int g = 0; g < 4; g++) {
                    acc[(0 * 4 + i) * 4 + g] = ffma2(wr[g * 2 + 0], v, acc[(0 * 4 + i) * 4 + g]);
                    acc[(1 * 4 + i) * 4 + g] = ffma2(wr[g * 2 + 1], v, acc[(1 * 4 + i) * 4 + g]);
                }
                fac[0 * 4 + i] = ffma2(wf0, v, fac[0 * 4 + i]);
                fac[1 * 4 + i] = ffma2(wf1, v, fac[1 * 4 + i]);
            }
        }

        // ===== intra-warp fold reduction over 16 k-slices =====
        #pragma unroll
        for (int r = 0; r < 4; r++) {
            const int mm = 8 >> r, half = 16 >> r;
            const bool hi = (ks & mm) != 0;
            #pragma unroll
            for (int i = 0; i < half; i++) {
                ull send = hi ? acc[i] : acc[i + half];
                ull recv = shflx(send, mm);
                acc[i] = add2(hi ? acc[i + half] : acc[i], recv);
            }
        }
        #pragma unroll
        for (int r = 0; r < 3; r++) {
            const int mm = 8 >> r, half = 4 >> r;
            const bool hi = (ks & mm) != 0;
            #pragma unroll
            for (int i = 0; i < half; i++) {
                ull send = hi ? fac[i] : fac[i + half];
                ull recv = shflx(send, mm);
                fac[i] = add2(hi ? fac[i + half] : fac[i], recv);
            }
        }
        ull pa = shflx(acc[0], 1), pb = shflx(acc[1], 1);
        float q0, q1, q2, q3;
        if ((ks & 1) == 0) { q0 = red2(acc[0]); q1 = red2(acc[1]); q2 = red2(pa);     q3 = red2(pb); }
        else               { q0 = red2(pa);     q1 = red2(pb);     q2 = red2(acc[0]); q3 = red2(acc[1]); }
        float fes = red2(fac[0]);
        fes += __shfl_xor_sync(0xffffffffu, fes, 1);

        // ===== deferred fe + activation + state update =====
        float fe = __expf(fes + bfj);
        float cr = cc * fe;
        float iv = sigm(q0 + bias0), fv = sigm(q1 + bias1);
        float gv = tanha(q2 + bias2), ov = sigm(q3 + bias3);
        cc = fv * cr + iv * gv;
        hv = ov * tanha(cc);

        const int p1 = (t + 1) & 1;
        if ((ks & 1) == 0) {
            out[((size_t)bl * TT + t) * HH + jl] = hv;
            __stcg(&g_Hbuf[p1][bl * HH + jl], hv);
        }

        // ===== x-part of gates(t+1) — no dependence on h_t, fills barrier slack =====
        #pragma unroll
        for (int i = 0; i < 32; i++) acc[i] = 0ull;
        if (t + 1 < TT) {
            #pragma unroll
            for (int m = 0; m < 4; m++) {
                ull wr[8];
                #pragma unroll
                for (int g = 0; g < 4; g++) {
                    wr[g * 2 + 0] = pw[(g * 16 + 0) * (WST/2) + m * 16];
                    wr[g * 2 + 1] = pw[(g * 16 + 1) * (WST/2) + m * 16];
                }
                #pragma unroll
                for (int i = 0; i < 4; i++) {
                    ull v = __ldg(xu + ((size_t)(bl0 + 2 * i) * TT + (t + 1)) * (II/2) + ks + m * 16);
                    #pragma unroll
                    for (int g = 0; g < 4; g++) {
                        acc[(0 * 4 + i) * 4 + g] = ffma2(wr[g * 2 + 0], v, acc[(0 * 4 + i) * 4 + g]);
                        acc[(1 * 4 + i) * 4 + g] = ffma2(wr[g * 2 + 1], v, acc[(1 * 4 + i) * 4 + g]);
                    }
                }
            }
        }
        __syncthreads();                          // S2: all h stores issued CTA-wide

        // ===== flag-array grid barrier (32 CTAs per batch group) =====
        if (tid == 0) {
            __threadfence();                      // release h writes
            asm volatile("st.global.cg.u32 [%0], %1;" :: "l"(myflag), "r"((unsigned)(t + 1)) : "memory");
        }
        if (tid < 32) {
            const unsigned target = (unsigned)(t + 1);
            while (ld_acq(flags + tid) < target) { }
        }
        __syncthreads();                          // S3

        // ===== stage h_t into SMEM =====
        {
            const float4* hb = (const float4*)g_Hbuf[p1];
            #pragma unroll
            for (int it = 0; it < (UB * HH / 4) / NTHR; it++) {
                int idx = tid + it * NTHR;
                int b = idx >> 7, k4 = idx & 127;
                float4 v = __ldcg(&hb[(size_t)(b0 + b) * (HH / 4) + k4]);
                *(float4*)(hx + b * HST + k4 * 4) = v;
            }
        }
        __syncthreads();                          // S4
    }

    // ===== epilogue: apply final fe(h_{T-1}) to raw c =====
    {
        ull fac[8];
        #pragma unroll
        for (int i = 0; i < 8; i++) fac[i] = 0ull;
        #pragma unroll
        for (int m = 0; m < 16; m++) {
            ull wf0 = __ldg(pwf + m * 16);
            ull wf1 = __ldg(pwf + 256 + m * 16);
            #pragma unroll
            for (int i = 0; i < 4; i++) {
                ull v = pv[i * HST + m * 16];
                fac[0 * 4 + i] = ffma2(wf0, v, fac[0 * 4 + i]);
                fac[1 * 4 + i] = ffma2(wf1, v, fac[1 * 4 + i]);
            }
        }
        #pragma unroll
        for (int r = 0; r < 3; r++) {
            const int mm = 8 >> r, half = 4 >> r;
            const bool hi = (ks & mm) != 0;
            #pragma unroll
            for (int i = 0; i < half; i++) {
                ull send = hi ? fac[i] : fac[i + half];
                ull recv = shflx(send, mm);
                fac[i] = add2(hi ? fac[i + half] : fac[i], recv);
            }
        }
        float fes = red2(fac[0]);
        fes += __shfl_xor_sync(0xffffffffu, fes, 1);
        cc *= __expf(fes + bfj);
    }

    // ===== final h, c (tuple flatten: out | h | c) =====
    if ((ks & 1) == 0 && out_elems >= (long long)BB * TT * HH + 2LL * BB * HH) {
        float* hout = out + (size_t)BB * TT * HH;
        float* cout = hout + (size_t)BB * HH;
        hout[bl * HH + jl] = hv;
        cout[bl * HH + jl] = cc;
    }
}

extern "C" void kernel_launch(void* const* d_in, const int* in_sizes, int n_in,
                              void* d_out, int out_size) {
    const float* x    = (const float*)d_in[0];
    const float* W_ih = (const float*)d_in[1];
    const float* W_hh = (const float*)d_in[2];
    const float* b_ih = (const float*)d_in[3];
    const float* b_hh = (const float*)d_in[4];
    const float* Wf   = (const float*)d_in[5];
    const float* bf   = (const float*)d_in[6];
    // d_in[7] = Wi, d_in[8] = bi: unused by the reference recurrence
    float* out = (float*)d_out;

    const size_t smem_bytes = (size_t)(64 * WST + UB * HST) * sizeof(float); // 197,376 B
    cudaFuncSetAttribute(sLSTM_70772471103948_kernel,
                         cudaFuncAttributeMaxDynamicSharedMemorySize, (int)smem_bytes);

    slstm_init_kernel<<<1, 128>>>();
    sLSTM_70772471103948_kernel<<<NCTA, NTHR, smem_bytes>>>(
        x, W_ih, W_hh, b_ih, b_hh, Wf, bf, out, (long long)out_size);
}

// round 17
// speedup vs baseline: 1.1357x; 1.1357x over previous
#include <cuda_runtime.h>
#include <cstddef>

// ---------------- problem constants ----------------
#define BB   64
#define TT   1024
#define II   128
#define HH   512
#define KK   640            // I + H

// ---------------- partitioning ----------------
#define GH   32             // hidden groups
#define GB   4              // batch groups
#define NCTA (GH*GB)        // 128 CTAs, one per SM, all resident
#define UH   16             // hidden units per CTA
#define UB   16             // batches per CTA
#define NTHR 512            // 16 warps: warp = (ug 0..7, bg2 0..1); lane = (ks 0..15, e 0..1)

#define WST  642            // weight row stride (floats), even -> ull rows aligned
#define HXST 644            // hx row stride: 16B-aligned rows

typedef unsigned long long ull;

// persistent state (no cudaMalloc allowed)
__device__ float    g_Hbuf[2][BB*HH];
__device__ unsigned g_flag[GB][32];   // per-group arrival flags, one 128B line per group

// ---------------- packed fp32x2 + fast helpers ----------------
__device__ __forceinline__ ull ffma2(ull a, ull b, ull c) {
    ull d;
    asm("fma.rn.f32x2 %0, %1, %2, %3;" : "=l"(d) : "l"(a), "l"(b), "l"(c));
    return d;
}
__device__ __forceinline__ ull add2(ull a, ull b) {
    ull d;
    asm("add.rn.f32x2 %0, %1, %2;" : "=l"(d) : "l"(a), "l"(b));
    return d;
}
__device__ __forceinline__ float red2(ull v) {
    return __uint_as_float((unsigned)v) + __uint_as_float((unsigned)(v >> 32));
}
__device__ __forceinline__ ull shflx(ull v, int m) {
    unsigned lo = (unsigned)v, hi = (unsigned)(v >> 32);
    lo = __shfl_xor_sync(0xffffffffu, lo, m);
    hi = __shfl_xor_sync(0xffffffffu, hi, m);
    return ((ull)hi << 32) | (ull)lo;
}
__device__ __forceinline__ float tanha(float x) {
    float y; asm("tanh.approx.f32 %0, %1;" : "=f"(y) : "f"(x)); return y;
}
__device__ __forceinline__ float sigm(float x) {
    return fmaf(tanha(0.5f * x), 0.5f, 0.5f);
}
__device__ __forceinline__ unsigned ld_acq(const unsigned* p) {
    unsigned v;
    asm volatile("ld.acquire.gpu.global.u32 %0, [%1];" : "=r"(v) : "l"(p) : "memory");
    return v;
}

__global__ void slstm_init_kernel() {
    if (threadIdx.x < GB * 32) ((unsigned*)g_flag)[threadIdx.x] = 0u;
}

// ---------------- persistent sLSTM kernel ----------------
extern "C" __global__ void __launch_bounds__(NTHR, 1)
sLSTM_70772471103948_kernel(const float* __restrict__ x,     // [B,T,I]
                            const float* __restrict__ W_ih,  // [4H,I]
                            const float* __restrict__ W_hh,  // [4H,H]
                            const float* __restrict__ b_ih,  // [4H]
                            const float* __restrict__ b_hh,  // [4H]
                            const float* __restrict__ Wf,    // [H,H]
                            const float* __restrict__ bf,    // [H]
                            float* __restrict__ out,         // [B,T,H] | h[B,H] | c[B,H]
                            long long out_elems)
{
    extern __shared__ float smem[];
    float* Wsm = smem;                           // 64 rows x WST (gate weights)
    float* hx  = smem + 64 * WST;                // 16 batch rows x HXST ([x_t | h_t])

    const int tid  = threadIdx.x;
    const int w    = tid >> 5;
    const int lane = tid & 31;
    const int ks   = lane & 15;                  // k-slice (strided chunks)
    const int e    = lane >> 4;                  // batch parity
    const int ug   = w & 7;                      // u-pair group (u in {2ug, 2ug+1})
    const int bg2  = w >> 3;                     // batch octet (0/1)
    const int hg   = blockIdx.x & (GH - 1);
    const int bg   = blockIdx.x >> 5;
    const int j0   = hg * UH;
    const int b0   = bg * UB;

    // lane's owned element after shfl reduction: elem = ks>>1 -> (uj, ib)
    const int uj = ks >> 3;
    const int ib = (ks >> 1) & 3;
    const int jl = j0 + 2 * ug + uj;             // owned hidden index
    const int bl = b0 + bg2 * 8 + 2 * ib + e;    // owned global batch

    // ---- stage gate weights into SMEM once ----
    for (int idx = tid; idx < 64 * KK; idx += NTHR) {
        int r  = idx / KK;
        int k  = idx - r * KK;
        int gg = r >> 4, uu = r & 15;
        int grow = gg * HH + j0 + uu;            // gate order: i,f,g,o
        float wv = (k < II) ? W_ih[grow * II + k] : W_hh[grow * HH + (k - II)];
        Wsm[r * WST + k] = wv;
    }
    // ---- stage x_0 ; h_0 = 0 ----
    {
        const float4* xs = (const float4*)x;
        int b = tid >> 5, k4 = tid & 31;          // 512 threads cover UB*II/4
        *(float4*)(hx + b * HXST + k4 * 4) =
            xs[((size_t)(b0 + b) * TT + 0) * (II / 4) + k4];
        float4 z = make_float4(0.f, 0.f, 0.f, 0.f);
        #pragma unroll
        for (int it = 0; it < (UB * HH / 4) / NTHR; it++) {
            int idx = tid + it * NTHR;
            int bb = idx >> 7, kk4 = idx & 127;
            *(float4*)(hx + bb * HXST + II + kk4 * 4) = z;
        }
    }
    const float bias0 = b_ih[0 * HH + jl] + b_hh[0 * HH + jl];
    const float bias1 = b_ih[1 * HH + jl] + b_hh[1 * HH + jl];
    const float bias2 = b_ih[2 * HH + jl] + b_hh[2 * HH + jl];
    const float bias3 = b_ih[3 * HH + jl] + b_hh[3 * HH + jl];
    const float bfj   = bf[jl];

    __syncthreads();

    // base pointers (lane-strided coalesced k)
    const ull* pw  = (const ull*)Wsm + (size_t)ug * WST + ks;            // + (g*16+u2)*321 + m*16
    const ull* pv  = (const ull*)hx + (size_t)(bg2 * 8 + e) * (HXST/2) + ks; // + i*HXST + m*16
    const ull* pwf = (const ull*)(Wf + (size_t)(j0 + 2 * ug) * HH) + ks; // + u2*256 + (m-4)*16

    unsigned* myflag = &g_flag[bg][hg];
    unsigned* flags  = &g_flag[bg][0];

    float cc = 0.f, hv = 0.f;                    // owned (jl, bl) state; cc RAW (fe deferred)

    #pragma unroll 1
    for (int t = 0; t < TT; t++) {
        // ===== gates + fused fe over this lane's k-slices =====
        ull acc[32];                             // idx = (uj*4 + i)*4 + g
        ull fac[8];                              // idx = uj*4 + i
        #pragma unroll
        for (int i = 0; i < 32; i++) acc[i] = 0ull;
        #pragma unroll
        for (int i = 0; i < 8; i++) fac[i] = 0ull;

        #pragma unroll
        for (int m = 0; m < 20; m++) {
            ull wr[8];
            #pragma unroll
            for (int g = 0; g < 4; g++) {
                wr[g * 2 + 0] = pw[(g * 16 + 0) * (WST/2) + m * 16];
                wr[g * 2 + 1] = pw[(g * 16 + 1) * (WST/2) + m * 16];
            }
            ull wf0 = 0ull, wf1 = 0ull;
            if (m >= 4) {                        // h-part: fold fe as a 5th gate
                wf0 = __ldg(pwf + (m - 4) * 16);
                wf1 = __ldg(pwf + 256 + (m - 4) * 16);
            }
            #pragma unroll
            for (int i = 0; i < 4; i++) {
                ull v = pv[i * HXST + m * 16];   // batch bg2*8 + 2i + e
                #pragma unroll
                for (int g = 0; g < 4; g++) {
                    acc[(0 * 4 + i) * 4 + g] = ffma2(wr[g * 2 + 0], v, acc[(0 * 4 + i) * 4 + g]);
                    acc[(1 * 4 + i) * 4 + g] = ffma2(wr[g * 2 + 1], v, acc[(1 * 4 + i) * 4 + g]);
                }
                if (m >= 4) {
                    fac[0 * 4 + i] = ffma2(wf0, v, fac[0 * 4 + i]);
                    fac[1 * 4 + i] = ffma2(wf1, v, fac[1 * 4 + i]);
                }
            }
        }

        // ===== intra-warp fold reduction over 16 k-slices =====
        #pragma unroll
        for (int r = 0; r < 4; r++) {
            const int mm = 8 >> r, half = 16 >> r;
            const bool hi = (ks & mm) != 0;
            #pragma unroll
            for (int i = 0; i < half; i++) {
                ull send = hi ? acc[i] : acc[i + half];
                ull recv = shflx(send, mm);
                acc[i] = add2(hi ? acc[i + half] : acc[i], recv);
            }
        }
        #pragma unroll
        for (int r = 0; r < 3; r++) {
            const int mm = 8 >> r, half = 4 >> r;
            const bool hi = (ks & mm) != 0;
            #pragma unroll
            for (int i = 0; i < half; i++) {
                ull send = hi ? fac[i] : fac[i + half];
                ull recv = shflx(send, mm);
                fac[i] = add2(hi ? fac[i + half] : fac[i], recv);
            }
        }
        // lane ks owns gate indices {2ks, 2ks+1}; pair-exchange to get all 4 gates
        ull pa = shflx(acc[0], 1), pb = shflx(acc[1], 1);
        float q0, q1, q2, q3;
        if ((ks & 1) == 0) { q0 = red2(acc[0]); q1 = red2(acc[1]); q2 = red2(pa);     q3 = red2(pb); }
        else               { q0 = red2(pa);     q1 = red2(pb);     q2 = red2(acc[0]); q3 = red2(acc[1]); }
        float fes = red2(fac[0]);
        fes += __shfl_xor_sync(0xffffffffu, fes, 1);

        // ===== deferred fe + activation + state update (dup across lane pair) =====
        float fe = __expf(fes + bfj);
        float cr = cc * fe;                      // fe(h_{t-1}) applied to raw c
        float iv = sigm(q0 + bias0), fv = sigm(q1 + bias1);
        float gv = tanha(q2 + bias2), ov = sigm(q3 + bias3);
        cc = fv * cr + iv * gv;
        hv = ov * tanha(cc);

        const int p1 = (t + 1) & 1;
        if ((ks & 1) == 0) {
            out[((size_t)bl * TT + t) * HH + jl] = hv;
            __stcg(&g_Hbuf[p1][bl * HH + jl], hv);
        }
        __syncthreads();                          // S2: h stores issued; hx reads finished

        // ===== signal barrier ASAP (shortest h-ready -> signal chain) =====
        if (tid == 0) {
            __threadfence();                      // release h writes
            asm volatile("st.global.cg.u32 [%0], %1;" :: "l"(myflag), "r"((unsigned)(t + 1)) : "memory");
        }

        // prefetch x_{t+1} into hx.x (safe: all hx.x reads done at S2; hidden under wait)
        if (t + 1 < TT) {
            const float4* xs = (const float4*)x;
            int b = tid >> 5, k4 = tid & 31;
            *(float4*)(hx + b * HXST + k4 * 4) =
                xs[((size_t)(b0 + b) * TT + (t + 1)) * (II / 4) + k4];
        }

        // ===== flag-array grid barrier wait (32 CTAs per batch group) =====
        if (tid < 32) {
            const unsigned target = (unsigned)(t + 1);
            while (ld_acq(flags + tid) < target) { }
        }
        __syncthreads();                          // S3

        // ===== stage h_t into SMEM =====
        {
            const float4* hb = (const float4*)g_Hbuf[p1];
            #pragma unroll
            for (int it = 0; it < (UB * HH / 4) / NTHR; it++) {
                int idx = tid + it * NTHR;
                int b = idx >> 7, k4 = idx & 127;
                float4 v = __ldcg(&hb[(size_t)(b0 + b) * (HH / 4) + k4]);
                *(float4*)(hx + b * HXST + II + k4 * 4) = v;
            }
        }
        __syncthreads();                          // S4
    }

    // ===== epilogue: apply final fe(h_{T-1}) to raw c =====
    {
        ull fac[8];
        #pragma unroll
        for (int i = 0; i < 8; i++) fac[i] = 0ull;
        #pragma unroll
        for (int m = 0; m < 16; m++) {
            ull wf0 = __ldg(pwf + m * 16);
            ull wf1 = __ldg(pwf + 256 + m * 16);
            #pragma unroll
            for (int i = 0; i < 4; i++) {
                ull v = pv[(II / 2) + i * HXST + m * 16];
                fac[0 * 4 + i] = ffma2(wf0, v, fac[0 * 4 + i]);
                fac[1 * 4 + i] = ffma2(wf1, v, fac[1 * 4 + i]);
            }
        }
        #pragma unroll
        for (int r = 0; r < 3; r++) {
            const int mm = 8 >> r, half = 4 >> r;
            const bool hi = (ks & mm) != 0;
            #pragma unroll
            for (int i = 0; i < half; i++) {
                ull send = hi ? fac[i] : fac[i + half];
                ull recv = shflx(send, mm);
                fac[i] = add2(hi ? fac[i + half] : fac[i], recv);
            }
        }
        float fes = red2(fac[0]);
        fes += __shfl_xor_sync(0xffffffffu, fes, 1);
        cc *= __expf(fes + bfj);
    }

    // ===== final h, c (tuple flatten: out | h | c) =====
    if ((ks & 1) == 0 && out_elems >= (long long)BB * TT * HH + 2LL * BB * HH) {
        float* hout = out + (size_t)BB * TT * HH;
        float* cout = hout + (size_t)BB * HH;
        hout[bl * HH + jl] = hv;
        cout[bl * HH + jl] = cc;
    }
}

extern "C" void kernel_launch(void* const* d_in, const int* in_sizes, int n_in,
                              void* d_out, int out_size) {
    const float* x    = (const float*)d_in[0];
    const float* W_ih = (const float*)d_in[1];
    const float* W_hh = (const float*)d_in[2];
    const float* b_ih = (const float*)d_in[3];
    const float* b_hh = (const float*)d_in[4];
    const float* Wf   = (const float*)d_in[5];
    const float* bf   = (const float*)d_in[6];
    // d_in[7] = Wi, d_in[8] = bi: unused by the reference recurrence
    float* out = (float*)d_out;

    const size_t smem_bytes = (size_t)(64 * WST + UB * HXST) * sizeof(float); // 205,568 B
    cudaFuncSetAttribute(sLSTM_70772471103948_kernel,
                         cudaFuncAttributeMaxDynamicSharedMemorySize, (int)smem_bytes);

    slstm_init_kernel<<<1, 128>>>();
    sLSTM_70772471103948_kernel<<<NCTA, NTHR, smem_bytes>>>(
        x, W_ih, W_hh, b_ih, b_hh, Wf, bf, out, (long long)out_size);
}